// round 14
// baseline (speedup 1.0000x reference)
#include <cuda_runtime.h>
#include <cstdint>

// Problem dims
static constexpr int Bn = 32, Tn = 10, Dn = 10, Un = 50, Pn = 50, En = 256;
static constexpr int Rr = 64;
static constexpr int SA  = 260;  // sX/sK row stride; 260%32==4
static constexpr int SSs = 68;   // sS row stride; 68%32==4
static constexpr int SVT = 68;   // sVT row stride (256 e-rows x (64 p + pad))
static constexpr int THREADS = 512;

static constexpr int OFF_X  = 0;
static constexpr int OFF_K  = Rr * SA;                 // 16640
static constexpr int OFF_VT = 2 * Rr * SA;             // 33280
static constexpr int OFF_S  = OFF_VT + 256 * SVT;      // 50688
static constexpr int SMEM_FLOATS = OFF_S + Rr * SSs;   // 55040
static constexpr int SMEM_BYTES  = SMEM_FLOATS * 4;    // 220160

// Pre-permuted, tf32-rounded weights: [w][n][perm(k)]  (L2-resident, read by all CTAs)
__device__ float Wp[2][256][256];

// in-32-block k permutation: sigma(k) = (k%4)*8 + (k%32)/4  (+ block base)
__device__ __forceinline__ int perm32(int c) { return (c & ~31) | (((c & 3) << 3) | ((c & 31) >> 2)); }
__device__ __forceinline__ int inv32lo(int l) { return ((l & 7) << 2) | ((l & 31) >> 3); }

__device__ __forceinline__ float wsum(float v) {
#pragma unroll
    for (int o = 16; o > 0; o >>= 1) v += __shfl_xor_sync(0xffffffffu, v, o);
    return v;
}
__device__ __forceinline__ float wmax(float v) {
#pragma unroll
    for (int o = 16; o > 0; o >>= 1) v = fmaxf(v, __shfl_xor_sync(0xffffffffu, v, o));
    return v;
}

// RNA tf32 rounding (producer-side, B operands)
__device__ __forceinline__ uint32_t f2tf(float f) {
    uint32_t r;
    asm("cvt.rna.tf32.f32 %0, %1;" : "=r"(r) : "f"(f));
    return r;
}
__device__ __forceinline__ float tfr(float f) { return __uint_as_float(f2tf(f)); }

#define F4E(v, i) ((i) == 0 ? (v).x : (i) == 1 ? (v).y : (i) == 2 ? (v).z : (v).w)
#define BITS(v, i) __float_as_uint(F4E(v, i))

__device__ __forceinline__ void mma_tf32(float c[4],
                                         uint32_t a0, uint32_t a1, uint32_t a2, uint32_t a3,
                                         uint32_t b0, uint32_t b1) {
    asm("mma.sync.aligned.m16n8k8.row.col.f32.tf32.tf32.f32 "
        "{%0,%1,%2,%3}, {%4,%5,%6,%7}, {%8,%9}, {%0,%1,%2,%3};"
        : "+f"(c[0]), "+f"(c[1]), "+f"(c[2]), "+f"(c[3])
        : "r"(a0), "r"(a1), "r"(a2), "r"(a3), "r"(b0), "r"(b1));
}

// FFN GEMM, barrier-free: C[64][256] = A[64][256] @ W^T.
// A in smem (E-permuted, stride SA). B loaded straight from Wp (L2) into
// registers, one-chunk prefetch. Warp tile m64 x n16 (nb = warp*16): each
// Wp line is read by exactly one warp per CTA.
// acc[mf][q][0..3]: C(16mf+g, nb+8q+2t), (.,+1), C(16mf+8+g, ..), (.,+1).
__device__ __forceinline__ void ffn_mma(
    int w, const float* __restrict__ sA, float acc[4][2][4], int warp, int g, int t)
{
    const float* wr0 = &Wp[w][warp * 16 + g][8 * t];      // q=0 row
    const float* wr1 = &Wp[w][warp * 16 + 8 + g][8 * t];  // q=1 row
    float4 bp[2][2];
    bp[0][0] = *reinterpret_cast<const float4*>(wr0);
    bp[0][1] = *reinterpret_cast<const float4*>(wr0 + 4);
    bp[1][0] = *reinterpret_cast<const float4*>(wr1);
    bp[1][1] = *reinterpret_cast<const float4*>(wr1 + 4);
#pragma unroll
    for (int c = 0; c < 8; ++c) {
        float4 bB[2][2];
        bB[0][0] = bp[0][0]; bB[0][1] = bp[0][1];
        bB[1][0] = bp[1][0]; bB[1][1] = bp[1][1];
        if (c < 7) {   // prefetch next chunk's B fragments from L2
            bp[0][0] = *reinterpret_cast<const float4*>(wr0 + (c + 1) * 32);
            bp[0][1] = *reinterpret_cast<const float4*>(wr0 + (c + 1) * 32 + 4);
            bp[1][0] = *reinterpret_cast<const float4*>(wr1 + (c + 1) * 32);
            bp[1][1] = *reinterpret_cast<const float4*>(wr1 + (c + 1) * 32 + 4);
        }
        const float* pA = sA + c * 32 + 8 * t;
#pragma unroll
        for (int half = 0; half < 2; ++half) {           // k8-half (sel)
            float4 aA[8];
#pragma unroll
            for (int r8 = 0; r8 < 8; ++r8)               // rows g, g+8, ..., g+56
                aA[r8] = *reinterpret_cast<const float4*>(pA + (r8 * 8 + g) * SA + half * 4);
#pragma unroll
            for (int hh = 0; hh < 2; ++hh) {
                const int e0 = 2 * hh, e1 = e0 + 1;
#pragma unroll
                for (int q = 0; q < 2; ++q) {
                    uint32_t b0 = BITS(bB[q][half], e0), b1 = BITS(bB[q][half], e1);
#pragma unroll
                    for (int mf = 0; mf < 4; ++mf) {
                        mma_tf32(acc[mf][q],
                                 BITS(aA[2 * mf], e0), BITS(aA[2 * mf + 1], e0),
                                 BITS(aA[2 * mf], e1), BITS(aA[2 * mf + 1], e1),
                                 b0, b1);
                    }
                }
            }
        }
    }
}

// ---- pre-pass: permute + tf32-round W1/W2 into Wp ----
__global__ void permute_w_kernel(const float* __restrict__ W1, const float* __restrict__ W2) {
    int r = blockIdx.x;              // 0..511
    int k = threadIdx.x;             // 0..255
    int n = r & 255;
    const float* W = (r < 256) ? W1 : W2;
    Wp[r >> 8][n][perm32(k)] = tfr(W[n * 256 + k]);
}

__global__ __launch_bounds__(THREADS, 1)
void fusion_block_kernel(
    const float* __restrict__ Qg_, const float* __restrict__ Kg_,
    const float* __restrict__ Vg_, const float* __restrict__ Mg_,
    const float* __restrict__ b1, const float* __restrict__ b2,
    const float* __restrict__ ln1w, const float* __restrict__ ln1b,
    const float* __restrict__ ln2w, const float* __restrict__ ln2b,
    float* __restrict__ Out)
{
    extern __shared__ float sm[];
    float* sX  = sm + OFF_X;    // Q -> x residual (E-permuted, fp32)
    float* sK  = sm + OFF_K;    // K (E-perm, rounded) -> H (E2-perm)
    float* sVT = sm + OFF_VT;   // V transposed [256 e][p-perm]
    float* sS  = sm + OFF_S;    // scores/probs (p-permuted cols)

    const int tid  = threadIdx.x;
    const int warp = tid >> 5;
    const int lane = tid & 31;
    const int g    = lane >> 2;
    const int t    = lane & 3;

    const int bid = blockIdx.x;
    const int bt  = bid / Dn;
    const int d   = bid - bt * Dn;
    const int b   = bt / Tn;
    const int bd  = b * Dn + d;

    const float* Qg = Qg_ + (size_t)bt  * (Un * En);
    const float* Kg = Kg_ + (size_t)bd  * (Pn * En);
    const float* Vg = Vg_ + (size_t)bd  * (Pn * En);
    const float* Mg = Mg_ + (size_t)bid * (Un * Pn);
    float*       Og = Out + (size_t)bid * (Un * En);

    const float4 z4 = make_float4(0.f, 0.f, 0.f, 0.f);

    // ---- Load Q,K (E-permuted granule assembly; K RNA-rounded) ----
#pragma unroll
    for (int it = 0; it < 2; ++it) {
        int idx = tid + it * THREADS;   // 64 rows x 16 half-blocks
        int row = idx & 63;
        int hb  = idx >> 6;
        float4 q[4], k[4];
#pragma unroll
        for (int m = 0; m < 4; ++m) {
            if (row < Un) {
                q[m] = *reinterpret_cast<const float4*>(Qg + row * En + hb * 16 + m * 4);
                k[m] = *reinterpret_cast<const float4*>(Kg + row * En + hb * 16 + m * 4);
            } else { q[m] = z4; k[m] = z4; }
        }
        int dst = row * SA + (hb >> 1) * 32 + (hb & 1) * 4;
#pragma unroll
        for (int j0 = 0; j0 < 4; ++j0) {
            *reinterpret_cast<float4*>(sX + dst + j0 * 8) =
                make_float4(F4E(q[0], j0), F4E(q[1], j0), F4E(q[2], j0), F4E(q[3], j0));
            *reinterpret_cast<float4*>(sK + dst + j0 * 8) =
                make_float4(tfr(F4E(k[0], j0)), tfr(F4E(k[1], j0)),
                            tfr(F4E(k[2], j0)), tfr(F4E(k[3], j0)));
        }
    }
    // ---- Load V transposed (RNA-rounded): sVT[e][perm(p)] ----
#pragma unroll
    for (int it = 0; it < 8; ++it) {
        int idx = tid + it * THREADS;   // 64 p x 64 e-quads
        int p   = idx & 63;
        int eq  = idx >> 6;
        float4 v = (p < Un) ? *reinterpret_cast<const float4*>(Vg + p * En + eq * 4) : z4;
        int sp = perm32(p);
#pragma unroll
        for (int j = 0; j < 4; ++j)
            sVT[(eq * 4 + j) * SVT + sp] = tfr(F4E(v, j));
    }
    __syncthreads();

    // ---- S = Q K^T / 16 + mask  (warp tile m32 x n8; 16 warps cover 64x64) ----
    {
        const int mbS = (warp & 1) * 32;
        const int nbS = (warp >> 1) * 8;
        float acc[2][4] = {};
#pragma unroll
        for (int kb = 0; kb < 8; ++kb) {
            float4 aA[4][2];
#pragma unroll
            for (int r4 = 0; r4 < 4; ++r4) {
                int row = mbS + (r4 & 1) * 8 + (r4 >> 1) * 16 + g;
                const float* p = sX + row * SA + kb * 32 + 8 * t;
                aA[r4][0] = *reinterpret_cast<const float4*>(p);
                aA[r4][1] = *reinterpret_cast<const float4*>(p + 4);
            }
            const float* pk = sK + (nbS + g) * SA + kb * 32 + 8 * t;
            float4 b0v = *reinterpret_cast<const float4*>(pk);
            float4 b1v = *reinterpret_cast<const float4*>(pk + 4);
#pragma unroll
            for (int h = 0; h < 4; ++h) {
                const int sel = h >> 1, e0 = 2 * (h & 1), e1 = e0 + 1;
                const float4& bb = sel ? b1v : b0v;
#pragma unroll
                for (int mf = 0; mf < 2; ++mf)
                    mma_tf32(acc[mf],
                             BITS(aA[2 * mf][sel], e0), BITS(aA[2 * mf + 1][sel], e0),
                             BITS(aA[2 * mf][sel], e1), BITS(aA[2 * mf + 1][sel], e1),
                             BITS(bb, e0), BITS(bb, e1));
            }
        }
        const float inv_scale = 1.0f / 16.0f;  // sqrt(256)+1e-8 == 16.0f
#pragma unroll
        for (int mf = 0; mf < 2; ++mf)
#pragma unroll
            for (int r = 0; r < 4; ++r) {
                int u = mbS + mf * 16 + g + (r >= 2 ? 8 : 0);
                int p = nbS + 2 * t + (r & 1);
                float s = acc[mf][r] * inv_scale;
                if (u < Un && p < Pn) s += Mg[u * Pn + p];
                sS[u * SSs + perm32(p)] = s;
            }
    }
    __syncthreads();

    // ---- softmax over p (cols p-permuted); probs RNA-rounded; 4 rows/warp ----
    {
        const bool val1 = (inv32lo(lane) < Pn - 32);
#pragma unroll
        for (int r = 0; r < 4; ++r) {
            int row = warp * 4 + r;
            float v0 = sS[row * SSs + lane];
            float v1 = val1 ? sS[row * SSs + lane + 32] : -1e30f;
            float m  = wmax(fmaxf(v0, v1));
            float e0 = __expf(v0 - m);
            float e1 = val1 ? __expf(v1 - m) : 0.f;
            float inv = 1.f / wsum(e0 + e1);
            sS[row * SSs + lane]      = tfr(e0 * inv);
            sS[row * SSs + lane + 32] = tfr(e1 * inv);
        }
    }
    __syncthreads();

    const int mb = (warp & 1) * 32;
    const int nb = (warp >> 1) * 32;

    // ---- v_att = S @ V (warp tile m32 x n32); x = Q + v_att ----
    {
        float acc[2][4][4] = {};
#pragma unroll
        for (int kb = 0; kb < 2; ++kb) {
            float4 aA[4][2];
#pragma unroll
            for (int r4 = 0; r4 < 4; ++r4) {
                int row = mb + (r4 & 1) * 8 + (r4 >> 1) * 16 + g;
                const float* p = sS + row * SSs + kb * 32 + 8 * t;
                aA[r4][0] = *reinterpret_cast<const float4*>(p);
                aA[r4][1] = *reinterpret_cast<const float4*>(p + 4);
            }
            float4 bB[4][2];
#pragma unroll
            for (int q = 0; q < 4; ++q) {
                const float* p = sVT + (nb + q * 8 + g) * SVT + kb * 32 + 8 * t;
                bB[q][0] = *reinterpret_cast<const float4*>(p);
                bB[q][1] = *reinterpret_cast<const float4*>(p + 4);
            }
#pragma unroll
            for (int h = 0; h < 4; ++h) {
                const int sel = h >> 1, e0 = 2 * (h & 1), e1 = e0 + 1;
#pragma unroll
                for (int q = 0; q < 4; ++q) {
                    uint32_t b0 = BITS(bB[q][sel], e0), b1 = BITS(bB[q][sel], e1);
#pragma unroll
                    for (int mf = 0; mf < 2; ++mf)
                        mma_tf32(acc[mf][q],
                                 BITS(aA[2 * mf][sel], e0), BITS(aA[2 * mf + 1][sel], e0),
                                 BITS(aA[2 * mf][sel], e1), BITS(aA[2 * mf + 1][sel], e1),
                                 b0, b1);
                }
            }
        }
#pragma unroll
        for (int mf = 0; mf < 2; ++mf)
#pragma unroll
            for (int q = 0; q < 4; ++q) {
                int row0 = mb + mf * 16 + g;
                int col  = nb + q * 8 + 2 * t;
                int sc0 = perm32(col), sc1 = perm32(col + 1);
                sX[row0 * SA + sc0]       += acc[mf][q][0];
                sX[row0 * SA + sc1]       += acc[mf][q][1];
                sX[(row0 + 8) * SA + sc0] += acc[mf][q][2];
                sX[(row0 + 8) * SA + sc1] += acc[mf][q][3];
            }
    }
    __syncthreads();

    // ---- LN1 (4 rows per warp; weights via inverse perm) ----
    {
#pragma unroll
        for (int r = 0; r < 4; ++r) {
            int row = warp * 4 + r;
            float xv[8];
            float s = 0.f;
#pragma unroll
            for (int kk = 0; kk < 8; ++kk) { xv[kk] = sX[row * SA + lane + kk * 32]; s += xv[kk]; }
            float mu = wsum(s) * (1.f / En);
            float vs = 0.f;
#pragma unroll
            for (int kk = 0; kk < 8; ++kk) { float t2 = xv[kk] - mu; vs += t2 * t2; }
            float rstd = rsqrtf(wsum(vs) * (1.f / En) + 1e-5f);
            int eb = inv32lo(lane);
#pragma unroll
            for (int kk = 0; kk < 8; ++kk) {
                int e = kk * 32 + eb;
                sX[row * SA + lane + kk * 32] = (xv[kk] - mu) * rstd * ln1w[e] + ln1b[e];
            }
        }
    }
    __syncthreads();   // LN1 writes visible before FFN1 reads sX

    // ---- FFN1: H = relu(x @ W1^T + b1) -> sK (E2-permuted); barrier-free GEMM ----
    {
        float acc[4][2][4] = {};
        ffn_mma(0, sX, acc, warp, g, t);
        const int nbF = warp * 16;
#pragma unroll
        for (int mf = 0; mf < 4; ++mf)
#pragma unroll
            for (int q = 0; q < 2; ++q) {
                int row0 = mf * 16 + g;
                int col  = nbF + q * 8 + 2 * t;
                float bb0 = __ldg(b1 + col), bb1 = __ldg(b1 + col + 1);
                int sc0 = perm32(col), sc1 = perm32(col + 1);
                sK[row0 * SA + sc0]       = fmaxf(acc[mf][q][0] + bb0, 0.f);
                sK[row0 * SA + sc1]       = fmaxf(acc[mf][q][1] + bb1, 0.f);
                sK[(row0 + 8) * SA + sc0] = fmaxf(acc[mf][q][2] + bb0, 0.f);
                sK[(row0 + 8) * SA + sc1] = fmaxf(acc[mf][q][3] + bb1, 0.f);
            }
    }
    __syncthreads();   // H complete before FFN2 reads it

    // ---- FFN2: y = H @ W2^T + b2 + x (into sX, fp32); barrier-free GEMM ----
    {
        float acc[4][2][4] = {};
        ffn_mma(1, sK, acc, warp, g, t);
        const int nbF = warp * 16;
#pragma unroll
        for (int mf = 0; mf < 4; ++mf)
#pragma unroll
            for (int q = 0; q < 2; ++q) {
                int row0 = mf * 16 + g;
                int col  = nbF + q * 8 + 2 * t;
                float bb0 = __ldg(b2 + col), bb1 = __ldg(b2 + col + 1);
                int sc0 = perm32(col), sc1 = perm32(col + 1);
                sX[row0 * SA + sc0]       += acc[mf][q][0] + bb0;
                sX[row0 * SA + sc1]       += acc[mf][q][1] + bb1;
                sX[(row0 + 8) * SA + sc0] += acc[mf][q][2] + bb0;
                sX[(row0 + 8) * SA + sc1] += acc[mf][q][3] + bb1;
            }
    }
    __syncthreads();

    // ---- LN2 + store (4 rows/warp; de-permute; line-coalesced) ----
    {
#pragma unroll
        for (int r = 0; r < 4; ++r) {
            int row = warp * 4 + r;
            if (row >= Un) continue;    // predicated; pad rows not stored
            float xv[8];
            float s = 0.f;
#pragma unroll
            for (int kk = 0; kk < 8; ++kk) { xv[kk] = sX[row * SA + lane + kk * 32]; s += xv[kk]; }
            float mu = wsum(s) * (1.f / En);
            float vs = 0.f;
#pragma unroll
            for (int kk = 0; kk < 8; ++kk) { float t2 = xv[kk] - mu; vs += t2 * t2; }
            float rstd = rsqrtf(wsum(vs) * (1.f / En) + 1e-5f);
            int eb = inv32lo(lane);
#pragma unroll
            for (int kk = 0; kk < 8; ++kk) {
                int e = kk * 32 + eb;
                Og[row * En + e] = (xv[kk] - mu) * rstd * ln2w[e] + ln2b[e];
            }
        }
    }
}

extern "C" void kernel_launch(void* const* d_in, const int* in_sizes, int n_in,
                              void* d_out, int out_size) {
    (void)in_sizes; (void)n_in; (void)out_size;
    permute_w_kernel<<<512, 256>>>((const float*)d_in[4], (const float*)d_in[6]);
    cudaFuncSetAttribute(fusion_block_kernel,
                         cudaFuncAttributeMaxDynamicSharedMemorySize, SMEM_BYTES);
    fusion_block_kernel<<<Bn * Tn * Dn, THREADS, SMEM_BYTES>>>(
        (const float*)d_in[0],  // Q
        (const float*)d_in[1],  // K
        (const float*)d_in[2],  // V
        (const float*)d_in[3],  // attention_mask
        (const float*)d_in[5],  // b1
        (const float*)d_in[7],  // b2
        (const float*)d_in[8],  // ln1_w
        (const float*)d_in[9],  // ln1_b
        (const float*)d_in[10], // ln2_w
        (const float*)d_in[11], // ln2_b
        (float*)d_out);
}

// round 15
// speedup vs baseline: 1.5189x; 1.5189x over previous
#include <cuda_runtime.h>
#include <cstdint>

// Problem dims
static constexpr int Bn = 32, Tn = 10, Dn = 10, Un = 50, Pn = 50, En = 256;
static constexpr int Rr = 64;
static constexpr int SA  = 260;  // sX/sK row stride; 260%32==4
static constexpr int SSs = 68;   // sS row stride; 68%32==4
static constexpr int SVT = 68;   // sVT row stride (256 e-rows x (64 p + pad))
static constexpr int THREADS = 512;

static constexpr int OFF_X  = 0;
static constexpr int OFF_K  = Rr * SA;                 // 16640
static constexpr int OFF_VT = 2 * Rr * SA;             // 33280
static constexpr int OFF_S  = OFF_VT + 256 * SVT;      // 50688
static constexpr int SMEM_FLOATS = OFF_S + Rr * SSs;   // 55040
static constexpr int SMEM_BYTES  = SMEM_FLOATS * 4;    // 220160

// Pre-permuted, tf32-rounded weights: [w][n][perm(k)]  (L2-resident, shared by all CTAs)
__device__ float Wp[2][256][256];

// in-32-block k permutation: sigma(k) = (k%4)*8 + (k%32)/4  (+ block base)
__device__ __forceinline__ int perm32(int c) { return (c & ~31) | (((c & 3) << 3) | ((c & 31) >> 2)); }
__device__ __forceinline__ int inv32lo(int l) { return ((l & 7) << 2) | ((l & 31) >> 3); }

__device__ __forceinline__ float wsum(float v) {
#pragma unroll
    for (int o = 16; o > 0; o >>= 1) v += __shfl_xor_sync(0xffffffffu, v, o);
    return v;
}
__device__ __forceinline__ float wmax(float v) {
#pragma unroll
    for (int o = 16; o > 0; o >>= 1) v = fmaxf(v, __shfl_xor_sync(0xffffffffu, v, o));
    return v;
}

// RNA tf32 rounding (producer-side, B operands)
__device__ __forceinline__ uint32_t f2tf(float f) {
    uint32_t r;
    asm("cvt.rna.tf32.f32 %0, %1;" : "=r"(r) : "f"(f));
    return r;
}
__device__ __forceinline__ float tfr(float f) { return __uint_as_float(f2tf(f)); }

#define F4E(v, i) ((i) == 0 ? (v).x : (i) == 1 ? (v).y : (i) == 2 ? (v).z : (v).w)
#define BITS(v, i) __float_as_uint(F4E(v, i))

__device__ __forceinline__ void mma_tf32(float c[4],
                                         uint32_t a0, uint32_t a1, uint32_t a2, uint32_t a3,
                                         uint32_t b0, uint32_t b1) {
    asm("mma.sync.aligned.m16n8k8.row.col.f32.tf32.tf32.f32 "
        "{%0,%1,%2,%3}, {%4,%5,%6,%7}, {%8,%9}, {%0,%1,%2,%3};"
        : "+f"(c[0]), "+f"(c[1]), "+f"(c[2]), "+f"(c[3])
        : "r"(a0), "r"(a1), "r"(a2), "r"(a3), "r"(b0), "r"(b1));
}

// FFN GEMM, barrier-free, m32 x n32 warp tile (R13 A-traffic, R14 W transport):
// C[64][256] = A[64][256] @ W^T. A in smem (E-permuted, stride SA);
// B straight from Wp (L2) into registers with one-chunk prefetch.
// mb=(warp&1)*32, nb=(warp>>1)*32; each Wp line read by 2 warps per CTA.
__device__ __forceinline__ void ffn_mma(
    int w, const float* __restrict__ sA, float acc[2][4][4],
    int mb, int nb, int g, int t)
{
    const float* wr[4];
#pragma unroll
    for (int q = 0; q < 4; ++q)
        wr[q] = &Wp[w][nb + q * 8 + g][8 * t];
    float4 bp[4][2];
#pragma unroll
    for (int q = 0; q < 4; ++q) {
        bp[q][0] = *reinterpret_cast<const float4*>(wr[q]);
        bp[q][1] = *reinterpret_cast<const float4*>(wr[q] + 4);
    }
#pragma unroll
    for (int c = 0; c < 8; ++c) {
        float4 bB[4][2];
#pragma unroll
        for (int q = 0; q < 4; ++q) { bB[q][0] = bp[q][0]; bB[q][1] = bp[q][1]; }
        if (c < 7) {   // prefetch next chunk's B fragments from L2
#pragma unroll
            for (int q = 0; q < 4; ++q) {
                bp[q][0] = *reinterpret_cast<const float4*>(wr[q] + (c + 1) * 32);
                bp[q][1] = *reinterpret_cast<const float4*>(wr[q] + (c + 1) * 32 + 4);
            }
        }
        float4 aA[4][2];
#pragma unroll
        for (int r4 = 0; r4 < 4; ++r4) {
            int row = mb + (r4 & 1) * 8 + (r4 >> 1) * 16 + g;
            const float* p = sA + row * SA + c * 32 + 8 * t;
            aA[r4][0] = *reinterpret_cast<const float4*>(p);
            aA[r4][1] = *reinterpret_cast<const float4*>(p + 4);
        }
#pragma unroll
        for (int h = 0; h < 4; ++h) {
            const int sel = h >> 1, e0 = 2 * (h & 1), e1 = e0 + 1;
#pragma unroll
            for (int q = 0; q < 4; ++q) {
                uint32_t b0 = BITS(bB[q][sel], e0), b1 = BITS(bB[q][sel], e1);
#pragma unroll
                for (int mf = 0; mf < 2; ++mf) {
                    mma_tf32(acc[mf][q],
                             BITS(aA[2 * mf][sel], e0), BITS(aA[2 * mf + 1][sel], e0),
                             BITS(aA[2 * mf][sel], e1), BITS(aA[2 * mf + 1][sel], e1),
                             b0, b1);
                }
            }
        }
    }
}

// ---- pre-pass: permute + tf32-round W1/W2 into Wp ----
__global__ void permute_w_kernel(const float* __restrict__ W1, const float* __restrict__ W2) {
    int r = blockIdx.x;              // 0..511
    int k = threadIdx.x;             // 0..255
    int n = r & 255;
    const float* W = (r < 256) ? W1 : W2;
    Wp[r >> 8][n][perm32(k)] = tfr(W[n * 256 + k]);
}

__global__ __launch_bounds__(THREADS, 1)
void fusion_block_kernel(
    const float* __restrict__ Qg_, const float* __restrict__ Kg_,
    const float* __restrict__ Vg_, const float* __restrict__ Mg_,
    const float* __restrict__ b1, const float* __restrict__ b2,
    const float* __restrict__ ln1w, const float* __restrict__ ln1b,
    const float* __restrict__ ln2w, const float* __restrict__ ln2b,
    float* __restrict__ Out)
{
    extern __shared__ float sm[];
    float* sX  = sm + OFF_X;    // Q -> x residual (E-permuted, fp32)
    float* sK  = sm + OFF_K;    // K (E-perm, rounded) -> H (E2-perm)
    float* sVT = sm + OFF_VT;   // V transposed [256 e][p-perm]
    float* sS  = sm + OFF_S;    // scores/probs (p-permuted cols)

    const int tid  = threadIdx.x;
    const int warp = tid >> 5;
    const int lane = tid & 31;
    const int g    = lane >> 2;
    const int t    = lane & 3;

    const int bid = blockIdx.x;
    const int bt  = bid / Dn;
    const int d   = bid - bt * Dn;
    const int b   = bt / Tn;
    const int bd  = b * Dn + d;

    const float* Qg = Qg_ + (size_t)bt  * (Un * En);
    const float* Kg = Kg_ + (size_t)bd  * (Pn * En);
    const float* Vg = Vg_ + (size_t)bd  * (Pn * En);
    const float* Mg = Mg_ + (size_t)bid * (Un * Pn);
    float*       Og = Out + (size_t)bid * (Un * En);

    const float4 z4 = make_float4(0.f, 0.f, 0.f, 0.f);

    // ---- Load Q,K (E-permuted granule assembly; K RNA-rounded) ----
#pragma unroll
    for (int it = 0; it < 2; ++it) {
        int idx = tid + it * THREADS;   // 64 rows x 16 half-blocks
        int row = idx & 63;
        int hb  = idx >> 6;
        float4 q[4], k[4];
#pragma unroll
        for (int m = 0; m < 4; ++m) {
            if (row < Un) {
                q[m] = *reinterpret_cast<const float4*>(Qg + row * En + hb * 16 + m * 4);
                k[m] = *reinterpret_cast<const float4*>(Kg + row * En + hb * 16 + m * 4);
            } else { q[m] = z4; k[m] = z4; }
        }
        int dst = row * SA + (hb >> 1) * 32 + (hb & 1) * 4;
#pragma unroll
        for (int j0 = 0; j0 < 4; ++j0) {
            *reinterpret_cast<float4*>(sX + dst + j0 * 8) =
                make_float4(F4E(q[0], j0), F4E(q[1], j0), F4E(q[2], j0), F4E(q[3], j0));
            *reinterpret_cast<float4*>(sK + dst + j0 * 8) =
                make_float4(tfr(F4E(k[0], j0)), tfr(F4E(k[1], j0)),
                            tfr(F4E(k[2], j0)), tfr(F4E(k[3], j0)));
        }
    }
    // ---- Load V transposed (RNA-rounded): sVT[e][perm(p)] ----
#pragma unroll
    for (int it = 0; it < 8; ++it) {
        int idx = tid + it * THREADS;   // 64 p x 64 e-quads
        int p   = idx & 63;
        int eq  = idx >> 6;
        float4 v = (p < Un) ? *reinterpret_cast<const float4*>(Vg + p * En + eq * 4) : z4;
        int sp = perm32(p);
#pragma unroll
        for (int j = 0; j < 4; ++j)
            sVT[(eq * 4 + j) * SVT + sp] = tfr(F4E(v, j));
    }
    __syncthreads();

    // ---- S = Q K^T / 16 + mask  (warp tile m32 x n8; 16 warps cover 64x64) ----
    {
        const int mbS = (warp & 1) * 32;
        const int nbS = (warp >> 1) * 8;
        float acc[2][4] = {};
#pragma unroll
        for (int kb = 0; kb < 8; ++kb) {
            float4 aA[4][2];
#pragma unroll
            for (int r4 = 0; r4 < 4; ++r4) {
                int row = mbS + (r4 & 1) * 8 + (r4 >> 1) * 16 + g;
                const float* p = sX + row * SA + kb * 32 + 8 * t;
                aA[r4][0] = *reinterpret_cast<const float4*>(p);
                aA[r4][1] = *reinterpret_cast<const float4*>(p + 4);
            }
            const float* pk = sK + (nbS + g) * SA + kb * 32 + 8 * t;
            float4 b0v = *reinterpret_cast<const float4*>(pk);
            float4 b1v = *reinterpret_cast<const float4*>(pk + 4);
#pragma unroll
            for (int h = 0; h < 4; ++h) {
                const int sel = h >> 1, e0 = 2 * (h & 1), e1 = e0 + 1;
                const float4& bb = sel ? b1v : b0v;
#pragma unroll
                for (int mf = 0; mf < 2; ++mf)
                    mma_tf32(acc[mf],
                             BITS(aA[2 * mf][sel], e0), BITS(aA[2 * mf + 1][sel], e0),
                             BITS(aA[2 * mf][sel], e1), BITS(aA[2 * mf + 1][sel], e1),
                             BITS(bb, e0), BITS(bb, e1));
            }
        }
        const float inv_scale = 1.0f / 16.0f;  // sqrt(256)+1e-8 == 16.0f
#pragma unroll
        for (int mf = 0; mf < 2; ++mf)
#pragma unroll
            for (int r = 0; r < 4; ++r) {
                int u = mbS + mf * 16 + g + (r >= 2 ? 8 : 0);
                int p = nbS + 2 * t + (r & 1);
                float s = acc[mf][r] * inv_scale;
                if (u < Un && p < Pn) s += Mg[u * Pn + p];
                sS[u * SSs + perm32(p)] = s;
            }
    }
    __syncthreads();

    // ---- softmax over p (cols p-permuted); probs RNA-rounded; 4 rows/warp ----
    {
        const bool val1 = (inv32lo(lane) < Pn - 32);
#pragma unroll
        for (int r = 0; r < 4; ++r) {
            int row = warp * 4 + r;
            float v0 = sS[row * SSs + lane];
            float v1 = val1 ? sS[row * SSs + lane + 32] : -1e30f;
            float m  = wmax(fmaxf(v0, v1));
            float e0 = __expf(v0 - m);
            float e1 = val1 ? __expf(v1 - m) : 0.f;
            float inv = 1.f / wsum(e0 + e1);
            sS[row * SSs + lane]      = tfr(e0 * inv);
            sS[row * SSs + lane + 32] = tfr(e1 * inv);
        }
    }
    __syncthreads();

    const int mb = (warp & 1) * 32;
    const int nb = (warp >> 1) * 32;

    // ---- v_att = S @ V (warp tile m32 x n32); x = Q + v_att ----
    {
        float acc[2][4][4] = {};
#pragma unroll
        for (int kb = 0; kb < 2; ++kb) {
            float4 aA[4][2];
#pragma unroll
            for (int r4 = 0; r4 < 4; ++r4) {
                int row = mb + (r4 & 1) * 8 + (r4 >> 1) * 16 + g;
                const float* p = sS + row * SSs + kb * 32 + 8 * t;
                aA[r4][0] = *reinterpret_cast<const float4*>(p);
                aA[r4][1] = *reinterpret_cast<const float4*>(p + 4);
            }
            float4 bB[4][2];
#pragma unroll
            for (int q = 0; q < 4; ++q) {
                const float* p = sVT + (nb + q * 8 + g) * SVT + kb * 32 + 8 * t;
                bB[q][0] = *reinterpret_cast<const float4*>(p);
                bB[q][1] = *reinterpret_cast<const float4*>(p + 4);
            }
#pragma unroll
            for (int h = 0; h < 4; ++h) {
                const int sel = h >> 1, e0 = 2 * (h & 1), e1 = e0 + 1;
#pragma unroll
                for (int q = 0; q < 4; ++q) {
                    uint32_t b0 = BITS(bB[q][sel], e0), b1 = BITS(bB[q][sel], e1);
#pragma unroll
                    for (int mf = 0; mf < 2; ++mf)
                        mma_tf32(acc[mf][q],
                                 BITS(aA[2 * mf][sel], e0), BITS(aA[2 * mf + 1][sel], e0),
                                 BITS(aA[2 * mf][sel], e1), BITS(aA[2 * mf + 1][sel], e1),
                                 b0, b1);
                }
            }
        }
#pragma unroll
        for (int mf = 0; mf < 2; ++mf)
#pragma unroll
            for (int q = 0; q < 4; ++q) {
                int row0 = mb + mf * 16 + g;
                int col  = nb + q * 8 + 2 * t;
                int sc0 = perm32(col), sc1 = perm32(col + 1);
                sX[row0 * SA + sc0]       += acc[mf][q][0];
                sX[row0 * SA + sc1]       += acc[mf][q][1];
                sX[(row0 + 8) * SA + sc0] += acc[mf][q][2];
                sX[(row0 + 8) * SA + sc1] += acc[mf][q][3];
            }
    }
    __syncthreads();

    // ---- LN1 (4 rows per warp; weights via inverse perm) ----
    {
#pragma unroll
        for (int r = 0; r < 4; ++r) {
            int row = warp * 4 + r;
            float xv[8];
            float s = 0.f;
#pragma unroll
            for (int kk = 0; kk < 8; ++kk) { xv[kk] = sX[row * SA + lane + kk * 32]; s += xv[kk]; }
            float mu = wsum(s) * (1.f / En);
            float vs = 0.f;
#pragma unroll
            for (int kk = 0; kk < 8; ++kk) { float t2 = xv[kk] - mu; vs += t2 * t2; }
            float rstd = rsqrtf(wsum(vs) * (1.f / En) + 1e-5f);
            int eb = inv32lo(lane);
#pragma unroll
            for (int kk = 0; kk < 8; ++kk) {
                int e = kk * 32 + eb;
                sX[row * SA + lane + kk * 32] = (xv[kk] - mu) * rstd * ln1w[e] + ln1b[e];
            }
        }
    }
    __syncthreads();   // LN1 writes visible before FFN1 reads sX

    // ---- FFN1: H = relu(x @ W1^T + b1) -> sK (E2-permuted); barrier-free GEMM ----
    {
        float acc[2][4][4] = {};
        ffn_mma(0, sX, acc, mb, nb, g, t);
#pragma unroll
        for (int mf = 0; mf < 2; ++mf)
#pragma unroll
            for (int q = 0; q < 4; ++q) {
                int row0 = mb + mf * 16 + g;
                int col  = nb + q * 8 + 2 * t;
                float bb0 = __ldg(b1 + col), bb1 = __ldg(b1 + col + 1);
                int sc0 = perm32(col), sc1 = perm32(col + 1);
                sK[row0 * SA + sc0]       = fmaxf(acc[mf][q][0] + bb0, 0.f);
                sK[row0 * SA + sc1]       = fmaxf(acc[mf][q][1] + bb1, 0.f);
                sK[(row0 + 8) * SA + sc0] = fmaxf(acc[mf][q][2] + bb0, 0.f);
                sK[(row0 + 8) * SA + sc1] = fmaxf(acc[mf][q][3] + bb1, 0.f);
            }
    }
    __syncthreads();   // H complete before FFN2 reads it

    // ---- FFN2: y = H @ W2^T + b2 + x (into sX, fp32); barrier-free GEMM ----
    {
        float acc[2][4][4] = {};
        ffn_mma(1, sK, acc, mb, nb, g, t);
#pragma unroll
        for (int mf = 0; mf < 2; ++mf)
#pragma unroll
            for (int q = 0; q < 4; ++q) {
                int row0 = mb + mf * 16 + g;
                int col  = nb + q * 8 + 2 * t;
                float bb0 = __ldg(b2 + col), bb1 = __ldg(b2 + col + 1);
                int sc0 = perm32(col), sc1 = perm32(col + 1);
                sX[row0 * SA + sc0]       += acc[mf][q][0] + bb0;
                sX[row0 * SA + sc1]       += acc[mf][q][1] + bb1;
                sX[(row0 + 8) * SA + sc0] += acc[mf][q][2] + bb0;
                sX[(row0 + 8) * SA + sc1] += acc[mf][q][3] + bb1;
            }
    }
    __syncthreads();

    // ---- LN2 + store (4 rows/warp; de-permute; line-coalesced) ----
    {
#pragma unroll
        for (int r = 0; r < 4; ++r) {
            int row = warp * 4 + r;
            if (row >= Un) continue;    // predicated; pad rows not stored
            float xv[8];
            float s = 0.f;
#pragma unroll
            for (int kk = 0; kk < 8; ++kk) { xv[kk] = sX[row * SA + lane + kk * 32]; s += xv[kk]; }
            float mu = wsum(s) * (1.f / En);
            float vs = 0.f;
#pragma unroll
            for (int kk = 0; kk < 8; ++kk) { float t2 = xv[kk] - mu; vs += t2 * t2; }
            float rstd = rsqrtf(wsum(vs) * (1.f / En) + 1e-5f);
            int eb = inv32lo(lane);
#pragma unroll
            for (int kk = 0; kk < 8; ++kk) {
                int e = kk * 32 + eb;
                Og[row * En + e] = (xv[kk] - mu) * rstd * ln2w[e] + ln2b[e];
            }
        }
    }
}

extern "C" void kernel_launch(void* const* d_in, const int* in_sizes, int n_in,
                              void* d_out, int out_size) {
    (void)in_sizes; (void)n_in; (void)out_size;
    permute_w_kernel<<<512, 256>>>((const float*)d_in[4], (const float*)d_in[6]);
    cudaFuncSetAttribute(fusion_block_kernel,
                         cudaFuncAttributeMaxDynamicSharedMemorySize, SMEM_BYTES);
    fusion_block_kernel<<<Bn * Tn * Dn, THREADS, SMEM_BYTES>>>(
        (const float*)d_in[0],  // Q
        (const float*)d_in[1],  // K
        (const float*)d_in[2],  // V
        (const float*)d_in[3],  // attention_mask
        (const float*)d_in[5],  // b1
        (const float*)d_in[7],  // b2
        (const float*)d_in[8],  // ln1_w
        (const float*)d_in[9],  // ln1_b
        (const float*)d_in[10], // ln2_w
        (const float*)d_in[11], // ln2_b
        (float*)d_out);
}